// round 6
// baseline (speedup 1.0000x reference)
#include <cuda_runtime.h>
#include <math.h>

// RepulsionLoss: points [4, 8192, 3] f32 -> scalar f32
// R6: 9-way row split of the grid-KNN. Each query's 3x3x3 cell block is 9
// contiguous x-rows; one thread per (query,row) -> ~14 candidates/thread,
// 294912 threads (~55 warps/SM). Exact top-8 recovered by smem merge of the
// 9 row-partials (rows partition the candidate set). Build kernel unchanged.

#define BATCH   4
#define NPTS    8192
#define KNN     8
#define RADIUS  0.07f
#define H2_INV  (1.0f / (0.03f * 0.03f))
#define ALPHA   0.1f

#define GRIDC   12
#define CPAD    2048

#define QPB     64                        // queries per knn block
#define NROW    9                         // (zz,yy) rows per query
#define KBLOCK  (QPB * NROW)              // 576 threads
#define KGRID   (BATCH * NPTS / QPB)      // 512 blocks
#define MSTRIDE (NROW * KNN + 1)          // 73: odd -> conflict-free columns

#define PPT     8                         // points per thread in build

__device__ int    g_off[BATCH][CPAD];
__device__ float4 g_sorted[BATCH][NPTS];
__device__ float        g_acc;            // zero-init; restored by finalize
__device__ unsigned int g_tick;           // ditto

static __device__ __forceinline__ int cell_coord(float v) {
    int c = (int)(v * (float)GRIDC);
    return c > GRIDC - 1 ? GRIDC - 1 : (c < 0 ? 0 : c);
}

// ---- 1: fused build: histogram + scan + scatter (1 block per batch) ----
__global__ __launch_bounds__(1024) void build_kernel(const float* __restrict__ pts) {
    __shared__ int s_cnt[CPAD];
    __shared__ int s_wsum[32];

    const int b   = blockIdx.x;
    const int tid = threadIdx.x;
    const int lane = tid & 31;
    const int warp = tid >> 5;
    const float* __restrict__ base = pts + (size_t)b * NPTS * 3;

    for (int i = tid; i < CPAD; i += 1024) s_cnt[i] = 0;
    __syncthreads();

    float px[PPT], py[PPT], pz[PPT];
    int   pc[PPT];
#pragma unroll
    for (int r = 0; r < PPT; ++r) {
        const int i = r * 1024 + tid;
        px[r] = __ldg(base + 3 * i + 0);
        py[r] = __ldg(base + 3 * i + 1);
        pz[r] = __ldg(base + 3 * i + 2);
        pc[r] = (cell_coord(pz[r]) * GRIDC + cell_coord(py[r])) * GRIDC
                + cell_coord(px[r]);
        atomicAdd(&s_cnt[pc[r]], 1);
    }
    __syncthreads();

    const int v0 = s_cnt[2 * tid];
    const int v1 = s_cnt[2 * tid + 1];
    int sum = v0 + v1;
    int inc = sum;
#pragma unroll
    for (int off = 1; off < 32; off <<= 1) {
        const int n = __shfl_up_sync(0xffffffffu, inc, off);
        if (lane >= off) inc += n;
    }
    if (lane == 31) s_wsum[warp] = inc;
    __syncthreads();
    if (warp == 0) {
        int wv = s_wsum[lane];
#pragma unroll
        for (int off = 1; off < 32; off <<= 1) {
            const int n = __shfl_up_sync(0xffffffffu, wv, off);
            if (lane >= off) wv += n;
        }
        s_wsum[lane] = wv;
    }
    __syncthreads();
    const int base_w = (warp > 0) ? s_wsum[warp - 1] : 0;
    const int ex = base_w + inc - sum;
    __syncthreads();
    s_cnt[2 * tid]     = ex;
    s_cnt[2 * tid + 1] = ex + v0;
    g_off[b][2 * tid]     = ex;
    g_off[b][2 * tid + 1] = ex + v0;
    __syncthreads();

#pragma unroll
    for (int r = 0; r < PPT; ++r) {
        const int pos = atomicAdd(&s_cnt[pc[r]], 1);
        g_sorted[b][pos] = make_float4(px[r], py[r], pz[r], 0.0f);
    }
}

// ---- 2: fused grid-KNN + loss (9 rows per query, one per thread) --------
__global__ __launch_bounds__(KBLOCK) void knn_kernel(float* __restrict__ out) {
    __shared__ float s_m[QPB][MSTRIDE];
    __shared__ float s_warp[2];

    const int tid    = threadIdx.x;
    const int ri     = tid / QPB;        // row index 0..8
    const int qlocal = tid % QPB;

    const int blocks_per_batch = NPTS / QPB;          // 128
    const int b  = blockIdx.x / blocks_per_batch;
    const int qi = (blockIdx.x % blocks_per_batch) * QPB + qlocal;

    const float4 p = __ldg(&g_sorted[b][qi]);
    const float qx = p.x, qy = p.y, qz = p.z;
    const int cx = cell_coord(qx);
    const int cy = cell_coord(qy);
    const int cz = cell_coord(qz);

    const int x0 = (cx > 0 ? cx - 1 : 0);
    const int x1 = (cx < GRIDC - 1 ? cx + 1 : GRIDC - 1);
    const int y0 = (cy > 0 ? cy - 1 : 0);
    const int y1 = (cy < GRIDC - 1 ? cy + 1 : GRIDC - 1);
    const int z0 = (cz > 0 ? cz - 1 : 0);
    const int z1 = (cz < GRIDC - 1 ? cz + 1 : GRIDC - 1);

    float best[KNN];                     // sorted ascending
#pragma unroll
    for (int k = 0; k < KNN; ++k) best[k] = 3.0e38f;

    const int zz = z0 + ri / 3;
    const int yy = y0 + ri % 3;
    if (zz <= z1 && yy <= y1) {
        const int rowbase = (zz * GRIDC + yy) * GRIDC;
        const int js = __ldg(&g_off[b][rowbase + x0]);
        const int je = __ldg(&g_off[b][rowbase + x1 + 1]);
#pragma unroll 2
        for (int j = js; j < je; ++j) {
            const float4 c = __ldg(&g_sorted[b][j]);
            const float dx = qx - c.x;
            const float dy = qy - c.y;
            const float dz = qz - c.z;
            const float d2 = fmaf(dx, dx, fmaf(dy, dy, dz * dz));
            if (d2 < best[KNN - 1]) {
                best[KNN - 1] = d2;
#pragma unroll
                for (int k = KNN - 1; k > 0; --k) {
                    const float lo = fminf(best[k - 1], best[k]);
                    const float hi = fmaxf(best[k - 1], best[k]);
                    best[k - 1] = lo;
                    best[k]     = hi;
                }
            }
        }
    }

    // publish row partials
#pragma unroll
    for (int k = 0; k < KNN; ++k) s_m[qlocal][ri * KNN + k] = best[k];
    __syncthreads();

    float s = 0.0f;
    if (ri == 0) {                        // threads 0..63 (warps 0-1) merge
        float m[KNN];
#pragma unroll
        for (int k = 0; k < KNN; ++k) m[k] = best[k];   // own row in regs
        for (int i = KNN; i < NROW * KNN; ++i) {
            const float d2 = s_m[qlocal][i];
            if (d2 < m[KNN - 1]) {
                m[KNN - 1] = d2;
#pragma unroll
                for (int k = KNN - 1; k > 0; --k) {
                    const float lo = fminf(m[k - 1], m[k]);
                    const float hi = fmaxf(m[k - 1], m[k]);
                    m[k - 1] = lo;
                    m[k]     = hi;
                }
            }
        }
        // unfilled slots (3e38) -> exp underflows to 0 -> contribute nothing
#pragma unroll
        for (int k = 0; k < KNN; ++k) {
            const float d2 = m[k];
            const float dn = sqrtf(fmaxf(d2, 1e-12f));
            const float w  = __expf(-d2 * H2_INV);
            s = fmaf(RADIUS - dn, w, s);
        }
#pragma unroll
        for (int off = 16; off > 0; off >>= 1)
            s += __shfl_xor_sync(0xffffffffu, s, off);
        if ((tid & 31) == 0) s_warp[tid >> 5] = s;      // warps 0,1
    }
    __syncthreads();

    if (tid == 0) {
        const float bs = s_warp[0] + s_warp[1];
        atomicAdd(&g_acc, bs);
        __threadfence();
        const unsigned t = atomicAdd(&g_tick, 1u);
        if (t == KGRID - 1) {                  // last block finalizes
            __threadfence();
            const float total = atomicAdd(&g_acc, 0.0f);
            out[0] = ALPHA * total * (1.0f / (float)(BATCH * NPTS * KNN));
            g_acc = 0.0f;                       // restore for graph replay
            __threadfence();
            g_tick = 0u;
        }
    }
}

extern "C" void kernel_launch(void* const* d_in, const int* in_sizes, int n_in,
                              void* d_out, int out_size) {
    const float* pts = (const float*)d_in[0];
    float* out = (float*)d_out;

    build_kernel<<<BATCH, 1024>>>(pts);
    knn_kernel  <<<KGRID, KBLOCK>>>(out);
}

// round 7
// speedup vs baseline: 1.0643x; 1.0643x over previous
#include <cuda_runtime.h>
#include <math.h>

// RepulsionLoss: points [4, 8192, 3] f32 -> scalar f32
// R7: branch-free top-8 insertion. For sorted ascending best[0..7]:
//     best'[0] = min(best[0], v); best'[k] = min(best[k], max(v, best[k-1]))
// 15 independent ops, depth 2, executed unconditionally per candidate --
// kills the predicated 56-cycle serial bubble chain that bound R5/R6.

#define BATCH   4
#define NPTS    8192
#define KNN     8
#define RADIUS  0.07f
#define H2_INV  (1.0f / (0.03f * 0.03f))
#define ALPHA   0.1f

#define GRIDC   12
#define CPAD    2048

#define QPB     64                        // queries per knn block
#define NROW    9                         // (zz,yy) rows per query
#define KBLOCK  (QPB * NROW)              // 576 threads
#define KGRID   (BATCH * NPTS / QPB)      // 512 blocks
#define MSTRIDE (NROW * KNN + 1)          // 73: conflict-free columns

#define PPT     8                         // points per thread in build

__device__ int    g_off[BATCH][CPAD];
__device__ float4 g_sorted[BATCH][NPTS];
__device__ float        g_acc;            // zero-init; restored by finalize
__device__ unsigned int g_tick;           // ditto

static __device__ __forceinline__ int cell_coord(float v) {
    int c = (int)(v * (float)GRIDC);
    return c > GRIDC - 1 ? GRIDC - 1 : (c < 0 ? 0 : c);
}

// branch-free sorted insert: independent across k, depth 2
static __device__ __forceinline__ void ins8(float best[KNN], float v) {
#pragma unroll
    for (int k = KNN - 1; k > 0; --k)
        best[k] = fminf(best[k], fmaxf(v, best[k - 1]));
    best[0] = fminf(best[0], v);
}

// ---- 1: fused build: histogram + scan + scatter (1 block per batch) ----
__global__ __launch_bounds__(1024) void build_kernel(const float* __restrict__ pts) {
    __shared__ int s_cnt[CPAD];
    __shared__ int s_wsum[32];

    const int b   = blockIdx.x;
    const int tid = threadIdx.x;
    const int lane = tid & 31;
    const int warp = tid >> 5;
    const float* __restrict__ base = pts + (size_t)b * NPTS * 3;

    for (int i = tid; i < CPAD; i += 1024) s_cnt[i] = 0;
    __syncthreads();

    float px[PPT], py[PPT], pz[PPT];
    int   pc[PPT];
#pragma unroll
    for (int r = 0; r < PPT; ++r) {
        const int i = r * 1024 + tid;
        px[r] = __ldg(base + 3 * i + 0);
        py[r] = __ldg(base + 3 * i + 1);
        pz[r] = __ldg(base + 3 * i + 2);
        pc[r] = (cell_coord(pz[r]) * GRIDC + cell_coord(py[r])) * GRIDC
                + cell_coord(px[r]);
        atomicAdd(&s_cnt[pc[r]], 1);
    }
    __syncthreads();

    const int v0 = s_cnt[2 * tid];
    const int v1 = s_cnt[2 * tid + 1];
    int sum = v0 + v1;
    int inc = sum;
#pragma unroll
    for (int off = 1; off < 32; off <<= 1) {
        const int n = __shfl_up_sync(0xffffffffu, inc, off);
        if (lane >= off) inc += n;
    }
    if (lane == 31) s_wsum[warp] = inc;
    __syncthreads();
    if (warp == 0) {
        int wv = s_wsum[lane];
#pragma unroll
        for (int off = 1; off < 32; off <<= 1) {
            const int n = __shfl_up_sync(0xffffffffu, wv, off);
            if (lane >= off) wv += n;
        }
        s_wsum[lane] = wv;
    }
    __syncthreads();
    const int base_w = (warp > 0) ? s_wsum[warp - 1] : 0;
    const int ex = base_w + inc - sum;
    __syncthreads();
    s_cnt[2 * tid]     = ex;
    s_cnt[2 * tid + 1] = ex + v0;
    g_off[b][2 * tid]     = ex;
    g_off[b][2 * tid + 1] = ex + v0;
    __syncthreads();

#pragma unroll
    for (int r = 0; r < PPT; ++r) {
        const int pos = atomicAdd(&s_cnt[pc[r]], 1);
        g_sorted[b][pos] = make_float4(px[r], py[r], pz[r], 0.0f);
    }
}

// ---- 2: fused grid-KNN + loss (9 rows per query, branch-free insert) ----
__global__ __launch_bounds__(KBLOCK) void knn_kernel(float* __restrict__ out) {
    __shared__ float s_m[QPB][MSTRIDE];
    __shared__ float s_warp[2];

    const int tid    = threadIdx.x;
    const int ri     = tid / QPB;        // row index 0..8
    const int qlocal = tid % QPB;

    const int blocks_per_batch = NPTS / QPB;          // 128
    const int b  = blockIdx.x / blocks_per_batch;
    const int qi = (blockIdx.x % blocks_per_batch) * QPB + qlocal;

    const float4 p = __ldg(&g_sorted[b][qi]);
    const float qx = p.x, qy = p.y, qz = p.z;
    const int cx = cell_coord(qx);
    const int cy = cell_coord(qy);
    const int cz = cell_coord(qz);

    const int x0 = (cx > 0 ? cx - 1 : 0);
    const int x1 = (cx < GRIDC - 1 ? cx + 1 : GRIDC - 1);
    const int y0 = (cy > 0 ? cy - 1 : 0);
    const int y1 = (cy < GRIDC - 1 ? cy + 1 : GRIDC - 1);
    const int z0 = (cz > 0 ? cz - 1 : 0);
    const int z1 = (cz < GRIDC - 1 ? cz + 1 : GRIDC - 1);

    float best[KNN];                     // sorted ascending
#pragma unroll
    for (int k = 0; k < KNN; ++k) best[k] = 3.0e38f;

    const int zz = z0 + ri / 3;
    const int yy = y0 + ri % 3;
    if (zz <= z1 && yy <= y1) {
        const int rowbase = (zz * GRIDC + yy) * GRIDC;
        const int js = __ldg(&g_off[b][rowbase + x0]);
        const int je = __ldg(&g_off[b][rowbase + x1 + 1]);
#pragma unroll 4
        for (int j = js; j < je; ++j) {
            const float4 c = __ldg(&g_sorted[b][j]);
            const float dx = qx - c.x;
            const float dy = qy - c.y;
            const float dz = qz - c.z;
            const float d2 = fmaf(dx, dx, fmaf(dy, dy, dz * dz));
            ins8(best, d2);              // unconditional, depth-2
        }
    }

    // publish row partials
#pragma unroll
    for (int k = 0; k < KNN; ++k) s_m[qlocal][ri * KNN + k] = best[k];
    __syncthreads();

    float s = 0.0f;
    if (ri == 0) {                        // threads 0..63 (warps 0-1) merge
        float m[KNN];
#pragma unroll
        for (int k = 0; k < KNN; ++k) m[k] = best[k];   // own row in regs
#pragma unroll 4
        for (int i = KNN; i < NROW * KNN; ++i)
            ins8(m, s_m[qlocal][i]);
        // unfilled slots (3e38) -> exp underflows to 0 -> contribute nothing
#pragma unroll
        for (int k = 0; k < KNN; ++k) {
            const float d2 = m[k];
            const float dn = sqrtf(fmaxf(d2, 1e-12f));
            const float w  = __expf(-d2 * H2_INV);
            s = fmaf(RADIUS - dn, w, s);
        }
#pragma unroll
        for (int off = 16; off > 0; off >>= 1)
            s += __shfl_xor_sync(0xffffffffu, s, off);
        if ((tid & 31) == 0) s_warp[tid >> 5] = s;      // warps 0,1
    }
    __syncthreads();

    if (tid == 0) {
        const float bs = s_warp[0] + s_warp[1];
        atomicAdd(&g_acc, bs);
        __threadfence();
        const unsigned t = atomicAdd(&g_tick, 1u);
        if (t == KGRID - 1) {                  // last block finalizes
            __threadfence();
            const float total = atomicAdd(&g_acc, 0.0f);
            out[0] = ALPHA * total * (1.0f / (float)(BATCH * NPTS * KNN));
            g_acc = 0.0f;                       // restore for graph replay
            __threadfence();
            g_tick = 0u;
        }
    }
}

extern "C" void kernel_launch(void* const* d_in, const int* in_sizes, int n_in,
                              void* d_out, int out_size) {
    const float* pts = (const float*)d_in[0];
    float* out = (float*)d_out;

    build_kernel<<<BATCH, 1024>>>(pts);
    knn_kernel  <<<KGRID, KBLOCK>>>(out);
}

// round 8
// speedup vs baseline: 1.1635x; 1.0932x over previous
#include <cuda_runtime.h>
#include <math.h>

// RepulsionLoss: points [4, 8192, 3] f32 -> scalar f32
// R8: GRIDC=14 (coverage radius 0.0714 > loss zero-crossing at dn=0.07 ->
// missed terms |.| < 1.1e-5), precomputed per-cell int2 row ranges, and
// single-wave knn launch (288-thread blocks, 7/SM, 1024 blocks all resident).

#define BATCH   4
#define NPTS    8192
#define KNN     8
#define RADIUS  0.07f
#define H2_INV  (1.0f / (0.03f * 0.03f))
#define ALPHA   0.1f

#define GRIDC   14
#define NCELL   (GRIDC * GRIDC * GRIDC)   // 2744
#define CPAD    4096

#define QPB     32                        // queries per knn block (one warp-lane each)
#define NROW    9                         // (zz,yy) rows per query -> warp ri = tid>>5
#define KBLOCK  (QPB * NROW)              // 288 threads, 9 warps
#define KGRID   (BATCH * NPTS / QPB)      // 1024 blocks  (<= 148*7: one wave)
#define MSTRIDE (NROW * KNN + 1)          // 73: gcd(73,32)=1 -> conflict-free

#define PPT     8                         // points per thread in build

__device__ int2   g_rr[BATCH][NCELL];     // per-cell x-row candidate range
__device__ float4 g_sorted[BATCH][NPTS];
__device__ float        g_acc;            // zero-init; restored by finalize
__device__ unsigned int g_tick;           // ditto

static __device__ __forceinline__ int cell_coord(float v) {
    int c = (int)(v * (float)GRIDC);
    return c > GRIDC - 1 ? GRIDC - 1 : (c < 0 ? 0 : c);
}

// branch-free sorted insert: independent across k, depth 2
static __device__ __forceinline__ void ins8(float best[KNN], float v) {
#pragma unroll
    for (int k = KNN - 1; k > 0; --k)
        best[k] = fminf(best[k], fmaxf(v, best[k - 1]));
    best[0] = fminf(best[0], v);
}

// ---- 1: fused build: histogram + scan + rowranges + scatter ------------
__global__ __launch_bounds__(1024) void build_kernel(const float* __restrict__ pts) {
    __shared__ int s_cnt[CPAD];           // counts -> offsets -> scatter cursors
    __shared__ int s_wsum[32];

    const int b    = blockIdx.x;
    const int tid  = threadIdx.x;
    const int lane = tid & 31;
    const int warp = tid >> 5;
    const float* __restrict__ base = pts + (size_t)b * NPTS * 3;

    for (int i = tid; i < CPAD; i += 1024) s_cnt[i] = 0;
    __syncthreads();

    float px[PPT], py[PPT], pz[PPT];
    int   pc[PPT];
#pragma unroll
    for (int r = 0; r < PPT; ++r) {
        const int i = r * 1024 + tid;
        px[r] = __ldg(base + 3 * i + 0);
        py[r] = __ldg(base + 3 * i + 1);
        pz[r] = __ldg(base + 3 * i + 2);
        pc[r] = (cell_coord(pz[r]) * GRIDC + cell_coord(py[r])) * GRIDC
                + cell_coord(px[r]);
        atomicAdd(&s_cnt[pc[r]], 1);
    }
    __syncthreads();

    // exclusive scan of 4096 counts, 4 per thread
    const int t4 = tid * 4;
    const int v0 = s_cnt[t4 + 0];
    const int v1 = s_cnt[t4 + 1];
    const int v2 = s_cnt[t4 + 2];
    const int v3 = s_cnt[t4 + 3];
    const int sum = v0 + v1 + v2 + v3;
    int inc = sum;
#pragma unroll
    for (int off = 1; off < 32; off <<= 1) {
        const int n = __shfl_up_sync(0xffffffffu, inc, off);
        if (lane >= off) inc += n;
    }
    if (lane == 31) s_wsum[warp] = inc;
    __syncthreads();
    if (warp == 0) {
        int wv = s_wsum[lane];
#pragma unroll
        for (int off = 1; off < 32; off <<= 1) {
            const int n = __shfl_up_sync(0xffffffffu, wv, off);
            if (lane >= off) wv += n;
        }
        s_wsum[lane] = wv;
    }
    __syncthreads();
    const int base_w = (warp > 0) ? s_wsum[warp - 1] : 0;
    const int ex = base_w + inc - sum;
    // each thread rewrites only the 4 cells it read: no cross-thread hazard
    s_cnt[t4 + 0] = ex;
    s_cnt[t4 + 1] = ex + v0;
    s_cnt[t4 + 2] = ex + v0 + v1;
    s_cnt[t4 + 3] = ex + v0 + v1 + v2;
    __syncthreads();

    // per-cell x-row candidate ranges (offsets are globally contiguous, so
    // off[row, x1+1] is valid even at x=GRIDC-1; off[NCELL]=NPTS from padding)
    for (int i = tid; i < NCELL; i += 1024) {
        const int x  = i % GRIDC;
        const int rb = i - x;
        const int xs = s_cnt[rb + (x > 0 ? x - 1 : 0)];
        const int xe = s_cnt[rb + (x < GRIDC - 1 ? x + 1 : GRIDC - 1) + 1];
        g_rr[b][i] = make_int2(xs, xe);
    }
    __syncthreads();

#pragma unroll
    for (int r = 0; r < PPT; ++r) {
        const int pos = atomicAdd(&s_cnt[pc[r]], 1);
        g_sorted[b][pos] = make_float4(px[r], py[r], pz[r], 0.0f);
    }
}

// ---- 2: fused grid-KNN + loss (9 rows/query, branch-free insert) -------
__global__ __launch_bounds__(KBLOCK, 7) void knn_kernel(float* __restrict__ out) {
    __shared__ float s_m[QPB][MSTRIDE];

    const int tid    = threadIdx.x;
    const int ri     = tid >> 5;          // row index 0..8 (= warp id)
    const int qlocal = tid & 31;          // lane = local query

    const int blocks_per_batch = NPTS / QPB;           // 256
    const int b  = blockIdx.x / blocks_per_batch;
    const int qi = (blockIdx.x % blocks_per_batch) * QPB + qlocal;

    const float4 p = __ldg(&g_sorted[b][qi]);
    const float qx = p.x, qy = p.y, qz = p.z;
    const int cx = cell_coord(qx);
    const int cy = cell_coord(qy);
    const int cz = cell_coord(qz);

    float best[KNN];                      // sorted ascending
#pragma unroll
    for (int k = 0; k < KNN; ++k) best[k] = 3.0e38f;

    const int zz = cz - 1 + ri / 3;
    const int yy = cy - 1 + ri % 3;
    if ((unsigned)zz < GRIDC && (unsigned)yy < GRIDC) {
        const int2 r = __ldg(&g_rr[b][(zz * GRIDC + yy) * GRIDC + cx]);
#pragma unroll 4
        for (int j = r.x; j < r.y; ++j) {
            const float4 c = __ldg(&g_sorted[b][j]);
            const float dx = qx - c.x;
            const float dy = qy - c.y;
            const float dz = qz - c.z;
            const float d2 = fmaf(dx, dx, fmaf(dy, dy, dz * dz));
            ins8(best, d2);               // unconditional, depth-2
        }
    }

    // publish row partials (stride-73 rows: conflict-free)
#pragma unroll
    for (int k = 0; k < KNN; ++k) s_m[qlocal][ri * KNN + k] = best[k];
    __syncthreads();

    if (ri == 0) {                        // warp 0 merges + reduces
        float m[KNN];
#pragma unroll
        for (int k = 0; k < KNN; ++k) m[k] = best[k];   // own row in regs
#pragma unroll 4
        for (int i = KNN; i < NROW * KNN; ++i)
            ins8(m, s_m[qlocal][i]);

        // unfilled slots (3e38) -> exp underflows to 0 -> contribute nothing
        float s = 0.0f;
#pragma unroll
        for (int k = 0; k < KNN; ++k) {
            const float d2 = m[k];
            const float dn = sqrtf(fmaxf(d2, 1e-12f));
            const float w  = __expf(-d2 * H2_INV);
            s = fmaf(RADIUS - dn, w, s);
        }
#pragma unroll
        for (int off = 16; off > 0; off >>= 1)
            s += __shfl_xor_sync(0xffffffffu, s, off);

        if (qlocal == 0) {
            atomicAdd(&g_acc, s);
            __threadfence();
            const unsigned t = atomicAdd(&g_tick, 1u);
            if (t == KGRID - 1) {              // last block finalizes
                __threadfence();
                const float total = atomicAdd(&g_acc, 0.0f);
                out[0] = ALPHA * total * (1.0f / (float)(BATCH * NPTS * KNN));
                g_acc = 0.0f;                   // restore for graph replay
                __threadfence();
                g_tick = 0u;
            }
        }
    }
}

extern "C" void kernel_launch(void* const* d_in, const int* in_sizes, int n_in,
                              void* d_out, int out_size) {
    const float* pts = (const float*)d_in[0];
    float* out = (float*)d_out;

    build_kernel<<<BATCH, 1024>>>(pts);
    knn_kernel  <<<KGRID, KBLOCK>>>(out);
}